// round 2
// baseline (speedup 1.0000x reference)
#include <cuda_runtime.h>
#include <cuda_fp16.h>
#include <cstdint>

// Problem dims
#define B_ 16
#define S_ 256
#define V_ 32000
#define H_ 1024

// ---------------- scratch (device globals — no runtime alloc) ----------------
__device__ __align__(256) float  g_h[2][B_ * H_];                 // ping-pong hidden state
__device__ __align__(256) __half g_Hall[B_ * S_ * H_];            // all h_t, fp16 (8 MB)
__device__ __align__(256) __half g_W16[(size_t)V_ * H_];          // Why in fp16 (64 MB)

// ---------------- helpers ----------------
__device__ __forceinline__ uint32_t smem_u32(const void* p) {
    uint32_t a;
    asm("{ .reg .u64 t; cvta.to.shared.u64 t, %1; cvt.u32.u64 %0, t; }" : "=r"(a) : "l"(p));
    return a;
}
#define SW128(off) ((off) ^ (((off) >> 3) & 0x70))

__device__ __forceinline__ float fw_tanh(float x) {
    const float BP = 8192.0f / 32767.0f;
    float xc = fminf(fmaxf(x, -1.0f), 1.0f);
    float a = fabsf(xc);
    return (a < BP) ? xc : copysignf(BP + (a - BP) * 0.75f, xc);
}

// ---------------- kernel: zero h0 ----------------
__global__ void zero_h0_kernel() {
    int i = blockIdx.x * blockDim.x + threadIdx.x;
    if (i < B_ * H_) g_h[0][i] = 0.0f;
}

// ---------------- kernel: Why -> fp16 ----------------
__global__ void cvt_why_kernel(const float* __restrict__ Why) {
    const size_t n4 = (size_t)V_ * H_ / 4;
    const float4* in = (const float4*)Why;
    __half2* out = (__half2*)g_W16;
    for (size_t i = (size_t)blockIdx.x * blockDim.x + threadIdx.x; i < n4;
         i += (size_t)gridDim.x * blockDim.x) {
        float4 v = in[i];
        out[2 * i]     = __floats2half2_rn(v.x, v.y);
        out[2 * i + 1] = __floats2half2_rn(v.z, v.w);
    }
}

// ---------------- kernel: one recurrence step (fp32) ----------------
// grid 128 CTAs x 256 thr; warp w handles output row h = blk*8 + w for all 16 batches.
__global__ __launch_bounds__(256) void step_kernel(const int* __restrict__ x_seq,
                                                   const float* __restrict__ Wxh,
                                                   const float* __restrict__ Whh,
                                                   int t) {
    int w = threadIdx.x >> 5;
    int l = threadIdx.x & 31;
    int h = blockIdx.x * 8 + w;

    const float4* hp4 = (const float4*)g_h[t & 1];
    const float4* W4  = (const float4*)(Whh + (size_t)h * H_);

    float acc[16];
#pragma unroll
    for (int b = 0; b < 16; b++) acc[b] = 0.0f;

#pragma unroll
    for (int i = 0; i < 8; i++) {
        float4 wv = W4[l + 32 * i];
#pragma unroll
        for (int b = 0; b < 16; b++) {
            float4 hv = hp4[b * 256 + l + 32 * i];
            acc[b] += wv.x * hv.x;
            acc[b] += wv.y * hv.y;
            acc[b] += wv.z * hv.z;
            acc[b] += wv.w * hv.w;
        }
    }
#pragma unroll
    for (int b = 0; b < 16; b++) {
#pragma unroll
        for (int off = 16; off >= 1; off >>= 1)
            acc[b] += __shfl_xor_sync(0xffffffffu, acc[b], off);
    }
    if (l < 16) {
        int b = l;
        int x = x_seq[b * S_ + t];
        float e = Wxh[(size_t)h * V_ + x];
        float hn = fw_tanh(acc[b] + e);
        g_h[(t + 1) & 1][b * H_ + h] = hn;
        g_Hall[((size_t)(b * S_ + t)) * H_ + h] = __float2half(hn);
    }
}

// ---------------- GEMM: logits[4096,32000] = Hall @ W16^T (fp16 in, fp32 acc) ----
// HMMA mma.sync.m16n8k16 path (base sm_103 ISA — no tcgen05).
// CTA tile 128x128, BK=64, 4-stage cp.async pipeline, SW128 swizzle.
static constexpr int BKB    = 128;            // bytes per smem row (64 fp16)
static constexpr int ASZ    = 128 * BKB;      // 16 KB per operand tile
static constexpr int STAGE  = 2 * ASZ;        // 32 KB per stage
static constexpr int STAGES = 4;              // 128 KB dynamic smem

__global__ __launch_bounds__(256, 1) void gemm_hmma(float* __restrict__ out) {
    extern __shared__ char sm[];
    const int tid  = threadIdx.x;
    const int lane = tid & 31;
    const int warp = tid >> 5;
    const int wm   = warp >> 2;   // 0..1
    const int wn   = warp & 3;    // 0..3
    const int m0   = blockIdx.y * 128;
    const int n0   = blockIdx.x * 128;
    const uint32_t sbase = smem_u32(sm);

    const char* Agb = (const char*)g_Hall + (size_t)m0 * (H_ * 2);
    const char* Bgb = (const char*)g_W16  + (size_t)n0 * (H_ * 2);

    // issue one K-stage of cp.async (A+B) then commit the group
    auto issue = [&](int kb) {
        if (kb < 16) {
            uint32_t sa = sbase + (kb & (STAGES - 1)) * STAGE;
            const char* Ag = Agb + kb * 128;   // kb*64 fp16 = 128 bytes
            const char* Bg = Bgb + kb * 128;
#pragma unroll
            for (int i = 0; i < 4; i++) {
                int chunk = tid + i * 256;             // 0..1023
                int row = chunk >> 3, col = chunk & 7; // row 0..127, 16B col 0..7
                uint32_t so = SW128((uint32_t)(row * BKB + col * 16));
                uint32_t d1 = sa + so;
                const char* g1 = Ag + (size_t)row * (H_ * 2) + col * 16;
                asm volatile("cp.async.cg.shared.global [%0], [%1], 16;" :: "r"(d1), "l"(g1));
                uint32_t d2 = sa + ASZ + so;
                const char* g2 = Bg + (size_t)row * (H_ * 2) + col * 16;
                asm volatile("cp.async.cg.shared.global [%0], [%1], 16;" :: "r"(d2), "l"(g2));
            }
        }
        asm volatile("cp.async.commit_group;");
    };

    issue(0); issue(1); issue(2);

    float acc[4][4][4];
#pragma unroll
    for (int mi = 0; mi < 4; mi++)
#pragma unroll
        for (int ni = 0; ni < 4; ni++)
#pragma unroll
            for (int r = 0; r < 4; r++) acc[mi][ni][r] = 0.0f;

    for (int kb = 0; kb < 16; kb++) {
        asm volatile("cp.async.wait_group 2;");
        __syncthreads();
        issue(kb + 3);

        uint32_t sa = sbase + (kb & (STAGES - 1)) * STAGE;
        uint32_t sb = sa + ASZ;

#pragma unroll
        for (int kk = 0; kk < 4; kk++) {
            uint32_t a[4][4];
#pragma unroll
            for (int mi = 0; mi < 4; mi++) {
                int row   = wm * 64 + mi * 16 + (lane & 15);
                int chunk = kk * 2 + (lane >> 4);
                uint32_t addr = sa + SW128((uint32_t)(row * BKB + chunk * 16));
                asm volatile("ldmatrix.sync.aligned.m8n8.x4.shared.b16 {%0,%1,%2,%3}, [%4];"
                             : "=r"(a[mi][0]), "=r"(a[mi][1]), "=r"(a[mi][2]), "=r"(a[mi][3])
                             : "r"(addr));
            }
            uint32_t b[4][2];
#pragma unroll
            for (int nj = 0; nj < 2; nj++) {
                int row   = wn * 32 + nj * 16 + ((lane >> 4) & 1) * 8 + (lane & 7);
                int chunk = kk * 2 + ((lane >> 3) & 1);
                uint32_t addr = sb + SW128((uint32_t)(row * BKB + chunk * 16));
                uint32_t r0, r1, r2, r3;
                asm volatile("ldmatrix.sync.aligned.m8n8.x4.shared.b16 {%0,%1,%2,%3}, [%4];"
                             : "=r"(r0), "=r"(r1), "=r"(r2), "=r"(r3) : "r"(addr));
                b[2 * nj][0] = r0; b[2 * nj][1] = r1;
                b[2 * nj + 1][0] = r2; b[2 * nj + 1][1] = r3;
            }
#pragma unroll
            for (int mi = 0; mi < 4; mi++)
#pragma unroll
                for (int ni = 0; ni < 4; ni++)
                    asm volatile(
                        "mma.sync.aligned.m16n8k16.row.col.f32.f16.f16.f32 "
                        "{%0,%1,%2,%3}, {%4,%5,%6,%7}, {%8,%9}, {%0,%1,%2,%3};"
                        : "+f"(acc[mi][ni][0]), "+f"(acc[mi][ni][1]),
                          "+f"(acc[mi][ni][2]), "+f"(acc[mi][ni][3])
                        : "r"(a[mi][0]), "r"(a[mi][1]), "r"(a[mi][2]), "r"(a[mi][3]),
                          "r"(b[ni][0]), "r"(b[ni][1]));
        }
    }

    // epilogue: direct fp32 stores (quad-contiguous 32B sectors)
#pragma unroll
    for (int mi = 0; mi < 4; mi++) {
        int row = m0 + wm * 64 + mi * 16 + (lane >> 2);
#pragma unroll
        for (int ni = 0; ni < 4; ni++) {
            int col = n0 + wn * 32 + ni * 8 + 2 * (lane & 3);
            float* p = out + (size_t)row * V_ + col;
            float2 v0 = make_float2(acc[mi][ni][0], acc[mi][ni][1]);
            float2 v1 = make_float2(acc[mi][ni][2], acc[mi][ni][3]);
            *(float2*)p              = v0;
            *(float2*)(p + 8 * (size_t)V_) = v1;
        }
    }
}

// ---------------- kernel: write h_final ----------------
__global__ void hfinal_kernel(float* __restrict__ out_tail) {
    int i = blockIdx.x * blockDim.x + threadIdx.x;
    if (i < B_ * H_) out_tail[i] = g_h[0][i];   // S=256 even -> final state in buffer 0
}

// ---------------- launch ----------------
extern "C" void kernel_launch(void* const* d_in, const int* in_sizes, int n_in,
                              void* d_out, int out_size) {
    const int*   x_seq = (const int*)d_in[0];
    const float* Wxh   = (const float*)d_in[1];
    const float* Whh   = (const float*)d_in[2];
    const float* Why   = (const float*)d_in[3];
    float* out = (float*)d_out;

    cudaFuncSetAttribute(gemm_hmma, cudaFuncAttributeMaxDynamicSharedMemorySize,
                         STAGES * STAGE);

    cvt_why_kernel<<<512, 256>>>(Why);
    zero_h0_kernel<<<(B_ * H_ + 255) / 256, 256>>>();

    for (int t = 0; t < S_; t++)
        step_kernel<<<128, 256>>>(x_seq, Wxh, Whh, t);

    dim3 grid(V_ / 128, (B_ * S_) / 128);  // (250, 32)
    gemm_hmma<<<grid, 256, STAGES * STAGE>>>(out);

    long long need = (long long)B_ * S_ * V_ + (long long)B_ * H_;
    if ((long long)out_size >= need)
        hfinal_kernel<<<(B_ * H_ + 255) / 256, 256>>>(out + (size_t)B_ * S_ * V_);
}

// round 3
// speedup vs baseline: 2.2832x; 2.2832x over previous
#include <cuda_runtime.h>
#include <cuda_fp16.h>
#include <cstdint>

// Problem dims
#define B_ 16
#define S_ 256
#define V_ 32000
#define H_ 1024

// ---------------- scratch (device globals — no runtime alloc) ----------------
__device__ __align__(256) float  g_hbuf[2][B_ * H_];              // ping-pong hidden state
__device__ __align__(256) __half g_Hall[B_ * S_ * H_];            // all h_t, fp16 (8 MB)
__device__ __align__(256) __half g_W16[(size_t)V_ * H_];          // Why in fp16 (64 MB)
__device__ int g_bar[S_];                                          // per-step barrier counters

// ---------------- helpers ----------------
__device__ __forceinline__ uint32_t smem_u32(const void* p) {
    uint32_t a;
    asm("{ .reg .u64 t; cvta.to.shared.u64 t, %1; cvt.u32.u64 %0, t; }" : "=r"(a) : "l"(p));
    return a;
}
#define SW128(off) ((off) ^ (((off) >> 3) & 0x70))

__device__ __forceinline__ float fw_tanh(float x) {
    const float BP = 8192.0f / 32767.0f;
    float xc = fminf(fmaxf(x, -1.0f), 1.0f);
    float a = fabsf(xc);
    return (a < BP) ? xc : copysignf(BP + (a - BP) * 0.75f, xc);
}

// ---------------- kernel: init (zero h0 + barrier counters) ----------------
__global__ void init_kernel() {
    int i = blockIdx.x * blockDim.x + threadIdx.x;
    if (i < B_ * H_) g_hbuf[0][i] = 0.0f;
    if (i < S_) g_bar[i] = 0;
}

// ---------------- kernel: Why -> fp16 ----------------
__global__ void cvt_why_kernel(const float* __restrict__ Why) {
    const size_t n4 = (size_t)V_ * H_ / 4;
    const float4* in = (const float4*)Why;
    __half2* out = (__half2*)g_W16;
    for (size_t i = (size_t)blockIdx.x * blockDim.x + threadIdx.x; i < n4;
         i += (size_t)gridDim.x * blockDim.x) {
        float4 v = in[i];
        out[2 * i]     = __floats2half2_rn(v.x, v.y);
        out[2 * i + 1] = __floats2half2_rn(v.z, v.w);
    }
}

// ---------------- persistent recurrence kernel ----------------
// 128 CTAs x 256 threads, all co-resident. CTA c owns h rows [c*8, c*8+8).
// smem: Whh rows (8x1024 f32, 32KB) loaded once + staged h (16x1024 f32, 64KB).
// Warp w: batch group bg=w>>1 (4 batches), row group rg=w&1 (4 rows).
__global__ __launch_bounds__(256, 1) void rnn_persist(const int* __restrict__ x_seq,
                                                      const float* __restrict__ Wxh,
                                                      const float* __restrict__ Whh) {
    extern __shared__ float sm[];
    float4* Wsm4 = (float4*)sm;                 // [8][256] float4
    float4* hsm4 = (float4*)(sm + 8 * H_);      // [16][256] float4

    const int c   = blockIdx.x;
    const int tid = threadIdx.x;
    const int w   = tid >> 5;
    const int l   = tid & 31;
    const int bg  = w >> 1;    // 0..3
    const int rg  = w & 1;     // 0..1

    // load this CTA's 8 Whh rows into smem (once)
    {
        const float4* Wg = (const float4*)(Whh + (size_t)c * 8 * H_);
#pragma unroll
        for (int i = 0; i < 8; i++) Wsm4[tid + 256 * i] = Wg[tid + 256 * i];
    }

    // per-lane output mapping (lanes 0..15 write results)
    const int ob   = bg * 4 + (l >> 2);          // batch
    const int orow = rg * 4 + (l & 3);           // local row 0..7
    const int hrow = c * 8 + orow;               // global h row
    const float* WxhRow = Wxh + (size_t)hrow * V_;

    for (int t = 0; t < S_; t++) {
        // embedding gather chain first (longest latency)
        float e = 0.0f;
        int x = 0;
        if (l < 16) x = x_seq[ob * S_ + t];

        // stage h_t into smem via cp.async (64KB, 16B per thread x16)
        {
            const char* hg = (const char*)g_hbuf[t & 1];
            uint32_t sdst = smem_u32(hsm4);
#pragma unroll
            for (int i = 0; i < 16; i++) {
                uint32_t d = sdst + (tid + 256 * i) * 16;
                const char* g = hg + (size_t)(tid + 256 * i) * 16;
                asm volatile("cp.async.cg.shared.global [%0], [%1], 16;" :: "r"(d), "l"(g));
            }
            asm volatile("cp.async.commit_group;");
        }

        if (l < 16) e = __ldg(WxhRow + x);

        asm volatile("cp.async.wait_group 0;");
        __syncthreads();

        // compute: acc[bi][ri] = dot(h[4bg+bi], W[4rg+ri]) partial over lane k-slice
        float acc[4][4];
#pragma unroll
        for (int bi = 0; bi < 4; bi++)
#pragma unroll
            for (int ri = 0; ri < 4; ri++) acc[bi][ri] = 0.0f;

#pragma unroll
        for (int i = 0; i < 8; i++) {
            float4 hv[4], wv[4];
#pragma unroll
            for (int bi = 0; bi < 4; bi++) hv[bi] = hsm4[(4 * bg + bi) * 256 + l + 32 * i];
#pragma unroll
            for (int ri = 0; ri < 4; ri++) wv[ri] = Wsm4[(4 * rg + ri) * 256 + l + 32 * i];
#pragma unroll
            for (int bi = 0; bi < 4; bi++)
#pragma unroll
                for (int ri = 0; ri < 4; ri++) {
                    acc[bi][ri] += hv[bi].x * wv[ri].x;
                    acc[bi][ri] += hv[bi].y * wv[ri].y;
                    acc[bi][ri] += hv[bi].z * wv[ri].z;
                    acc[bi][ri] += hv[bi].w * wv[ri].w;
                }
        }

        // butterfly reduce each acc across 32 lanes
#pragma unroll
        for (int bi = 0; bi < 4; bi++)
#pragma unroll
            for (int ri = 0; ri < 4; ri++)
#pragma unroll
                for (int off = 16; off >= 1; off >>= 1)
                    acc[bi][ri] += __shfl_xor_sync(0xffffffffu, acc[bi][ri], off);

        if (l < 16) {
            float hn = fw_tanh(acc[l >> 2][l & 3] + e);
            g_hbuf[(t + 1) & 1][ob * H_ + hrow] = hn;
            g_Hall[((size_t)(ob * S_ + t)) * H_ + hrow] = __float2half(hn);
        }

        // grid barrier (skip after last step; stream order covers downstream kernels)
        if (t < S_ - 1) {
            __threadfence();
            __syncthreads();
            if (tid == 0) {
                asm volatile("red.release.gpu.global.add.s32 [%0], 1;"
                             :: "l"(&g_bar[t]) : "memory");
                int v;
                do {
                    asm volatile("ld.acquire.gpu.global.s32 %0, [%1];"
                                 : "=r"(v) : "l"(&g_bar[t]) : "memory");
                    if (v >= 128) break;
                    __nanosleep(100);
                } while (true);
            }
            __syncthreads();
        }
    }
}

// ---------------- GEMM: logits[4096,32000] = Hall @ W16^T (fp16 in, fp32 acc) ----
// HMMA mma.sync.m16n8k16, CTA tile 128x128, BK=64, 3-stage cp.async (96KB -> 2 CTA/SM).
static constexpr int BKB    = 128;            // bytes per smem row (64 fp16)
static constexpr int ASZ    = 128 * BKB;      // 16 KB per operand tile
static constexpr int STAGE  = 2 * ASZ;        // 32 KB per stage
static constexpr int STAGES = 3;              // 96 KB dynamic smem

__global__ __launch_bounds__(256, 2) void gemm_hmma(float* __restrict__ out) {
    extern __shared__ char smc[];
    const int tid  = threadIdx.x;
    const int lane = tid & 31;
    const int warp = tid >> 5;
    const int wm   = warp >> 2;   // 0..1
    const int wn   = warp & 3;    // 0..3
    const int m0   = blockIdx.x * 128;   // m fast -> consecutive CTAs share B tile
    const int n0   = blockIdx.y * 128;
    const uint32_t sbase = smem_u32(smc);

    const char* Agb = (const char*)g_Hall + (size_t)m0 * (H_ * 2);
    const char* Bgb = (const char*)g_W16  + (size_t)n0 * (H_ * 2);

    auto issue = [&](int kb) {
        if (kb < 16) {
            uint32_t sa = sbase + (kb % STAGES) * STAGE;
            const char* Ag = Agb + kb * 128;
            const char* Bg = Bgb + kb * 128;
#pragma unroll
            for (int i = 0; i < 4; i++) {
                int chunk = tid + i * 256;
                int row = chunk >> 3, col = chunk & 7;
                uint32_t so = SW128((uint32_t)(row * BKB + col * 16));
                uint32_t d1 = sa + so;
                const char* g1 = Ag + (size_t)row * (H_ * 2) + col * 16;
                asm volatile("cp.async.cg.shared.global [%0], [%1], 16;" :: "r"(d1), "l"(g1));
                uint32_t d2 = sa + ASZ + so;
                const char* g2 = Bg + (size_t)row * (H_ * 2) + col * 16;
                asm volatile("cp.async.cg.shared.global [%0], [%1], 16;" :: "r"(d2), "l"(g2));
            }
        }
        asm volatile("cp.async.commit_group;");
    };

    issue(0); issue(1); issue(2);

    float acc[4][4][4];
#pragma unroll
    for (int mi = 0; mi < 4; mi++)
#pragma unroll
        for (int ni = 0; ni < 4; ni++)
#pragma unroll
            for (int r = 0; r < 4; r++) acc[mi][ni][r] = 0.0f;

    for (int kb = 0; kb < 16; kb++) {
        asm volatile("cp.async.wait_group 2;");
        __syncthreads();

        uint32_t sa = sbase + (kb % STAGES) * STAGE;
        uint32_t sb = sa + ASZ;

#pragma unroll
        for (int kk = 0; kk < 4; kk++) {
            uint32_t a[4][4];
#pragma unroll
            for (int mi = 0; mi < 4; mi++) {
                int row   = wm * 64 + mi * 16 + (lane & 15);
                int chunk = kk * 2 + (lane >> 4);
                uint32_t addr = sa + SW128((uint32_t)(row * BKB + chunk * 16));
                asm volatile("ldmatrix.sync.aligned.m8n8.x4.shared.b16 {%0,%1,%2,%3}, [%4];"
                             : "=r"(a[mi][0]), "=r"(a[mi][1]), "=r"(a[mi][2]), "=r"(a[mi][3])
                             : "r"(addr));
            }
            uint32_t b[4][2];
#pragma unroll
            for (int nj = 0; nj < 2; nj++) {
                int row   = wn * 32 + nj * 16 + ((lane >> 4) & 1) * 8 + (lane & 7);
                int chunk = kk * 2 + ((lane >> 3) & 1);
                uint32_t addr = sb + SW128((uint32_t)(row * BKB + chunk * 16));
                uint32_t r0, r1, r2, r3;
                asm volatile("ldmatrix.sync.aligned.m8n8.x4.shared.b16 {%0,%1,%2,%3}, [%4];"
                             : "=r"(r0), "=r"(r1), "=r"(r2), "=r"(r3) : "r"(addr));
                b[2 * nj][0] = r0; b[2 * nj][1] = r1;
                b[2 * nj + 1][0] = r2; b[2 * nj + 1][1] = r3;
            }
#pragma unroll
            for (int mi = 0; mi < 4; mi++)
#pragma unroll
                for (int ni = 0; ni < 4; ni++)
                    asm volatile(
                        "mma.sync.aligned.m16n8k16.row.col.f32.f16.f16.f32 "
                        "{%0,%1,%2,%3}, {%4,%5,%6,%7}, {%8,%9}, {%0,%1,%2,%3};"
                        : "+f"(acc[mi][ni][0]), "+f"(acc[mi][ni][1]),
                          "+f"(acc[mi][ni][2]), "+f"(acc[mi][ni][3])
                        : "r"(a[mi][0]), "r"(a[mi][1]), "r"(a[mi][2]), "r"(a[mi][3]),
                          "r"(b[ni][0]), "r"(b[ni][1]));
        }

        __syncthreads();     // everyone done reading stage kb%3 before overwrite
        issue(kb + 3);
    }

    // epilogue: direct fp32 stores
#pragma unroll
    for (int mi = 0; mi < 4; mi++) {
        int row = m0 + wm * 64 + mi * 16 + (lane >> 2);
#pragma unroll
        for (int ni = 0; ni < 4; ni++) {
            int col = n0 + wn * 32 + ni * 8 + 2 * (lane & 3);
            float* p = out + (size_t)row * V_ + col;
            *(float2*)p                    = make_float2(acc[mi][ni][0], acc[mi][ni][1]);
            *(float2*)(p + 8 * (size_t)V_) = make_float2(acc[mi][ni][2], acc[mi][ni][3]);
        }
    }
}

// ---------------- kernel: write h_final ----------------
__global__ void hfinal_kernel(float* __restrict__ out_tail) {
    int i = blockIdx.x * blockDim.x + threadIdx.x;
    if (i < B_ * H_) out_tail[i] = g_hbuf[0][i];   // t=255 wrote buffer (256)&1 = 0
}

// ---------------- launch ----------------
extern "C" void kernel_launch(void* const* d_in, const int* in_sizes, int n_in,
                              void* d_out, int out_size) {
    const int*   x_seq = (const int*)d_in[0];
    const float* Wxh   = (const float*)d_in[1];
    const float* Whh   = (const float*)d_in[2];
    const float* Why   = (const float*)d_in[3];
    float* out = (float*)d_out;

    cudaFuncSetAttribute(gemm_hmma, cudaFuncAttributeMaxDynamicSharedMemorySize,
                         STAGES * STAGE);
    cudaFuncSetAttribute(rnn_persist, cudaFuncAttributeMaxDynamicSharedMemorySize,
                         (8 + 16) * H_ * (int)sizeof(float));

    cvt_why_kernel<<<512, 256>>>(Why);
    init_kernel<<<(B_ * H_ + 255) / 256, 256>>>();

    rnn_persist<<<128, 256, (8 + 16) * H_ * sizeof(float)>>>(x_seq, Wxh, Whh);

    dim3 grid((B_ * S_) / 128, V_ / 128);  // (32, 250): m fast
    gemm_hmma<<<grid, 256, STAGES * STAGE>>>(out);

    long long need = (long long)B_ * S_ * V_ + (long long)B_ * H_;
    if ((long long)out_size >= need)
        hfinal_kernel<<<(B_ * H_ + 255) / 256, 256>>>(out + (size_t)B_ * S_ * V_);
}

// round 4
// speedup vs baseline: 2.6663x; 1.1678x over previous
#include <cuda_runtime.h>
#include <cuda_fp16.h>
#include <cstdint>

// Problem dims
#define B_ 16
#define S_ 256
#define V_ 32000
#define H_ 1024

// ---------------- scratch (device globals — no runtime alloc) ----------------
__device__ __align__(256) float  g_hbuf[2][B_ * H_];              // ping-pong hidden state
__device__ __align__(256) __half g_Hall[B_ * S_ * H_];            // all h_t, fp16 (8 MB)
__device__ __align__(256) __half g_W16[(size_t)V_ * H_];          // Why in fp16 (64 MB)
__device__ int g_bar[S_];                                          // per-step barrier counters

// ---------------- helpers ----------------
__device__ __forceinline__ uint32_t smem_u32(const void* p) {
    uint32_t a;
    asm("{ .reg .u64 t; cvta.to.shared.u64 t, %1; cvt.u32.u64 %0, t; }" : "=r"(a) : "l"(p));
    return a;
}
#define SW128(off) ((off) ^ (((off) >> 3) & 0x70))

__device__ __forceinline__ void ffma2(unsigned long long& d, unsigned long long a,
                                      unsigned long long b) {
    asm("fma.rn.f32x2 %0, %1, %2, %0;" : "+l"(d) : "l"(a), "l"(b));
}
__device__ __forceinline__ float unpack_sum(unsigned long long v) {
    float lo, hi;
    asm("mov.b64 {%0, %1}, %2;" : "=f"(lo), "=f"(hi) : "l"(v));
    return lo + hi;
}

__device__ __forceinline__ float fw_tanh(float x) {
    const float BP = 8192.0f / 32767.0f;
    float xc = fminf(fmaxf(x, -1.0f), 1.0f);
    float a = fabsf(xc);
    return (a < BP) ? xc : copysignf(BP + (a - BP) * 0.75f, xc);
}

// ---------------- kernel: init (zero h0 + barrier counters) ----------------
__global__ void init_kernel() {
    int i = blockIdx.x * blockDim.x + threadIdx.x;
    if (i < B_ * H_) g_hbuf[0][i] = 0.0f;
    if (i < S_) g_bar[i] = 0;
}

// ---------------- kernel: Why -> fp16 ----------------
__global__ void cvt_why_kernel(const float* __restrict__ Why) {
    const size_t n4 = (size_t)V_ * H_ / 4;
    const float4* in = (const float4*)Why;
    __half2* out = (__half2*)g_W16;
    for (size_t i = (size_t)blockIdx.x * blockDim.x + threadIdx.x; i < n4;
         i += (size_t)gridDim.x * blockDim.x) {
        float4 v = in[i];
        out[2 * i]     = __floats2half2_rn(v.x, v.y);
        out[2 * i + 1] = __floats2half2_rn(v.z, v.w);
    }
}

// ---------------- persistent recurrence kernel (v2) ----------------
// 128 CTAs x 256 threads. CTA c owns h rows [c*8, c*8+8).
// Whh rows live in REGISTERS (warp w: rows rg*4..rg*4+3, rg=w&1; lane k-slice).
// smem: staged h only (16 batches x 1024 f32 = 64KB).
// Warp w computes batches bg*4..bg*4+3 (bg=w>>1) x 4 rows.
__global__ __launch_bounds__(256, 1) void rnn_persist(const int* __restrict__ x_seq,
                                                      const float* __restrict__ Wxh,
                                                      const float* __restrict__ Whh) {
    extern __shared__ float sm[];
    ulonglong2* hsm2 = (ulonglong2*)sm;          // [16][256] 16B units

    const int c   = blockIdx.x;
    const int tid = threadIdx.x;
    const int w   = tid >> 5;
    const int l   = tid & 31;
    const int bg  = w >> 1;    // 0..3
    const int rg  = w & 1;     // 0..1

    // Whh slice -> registers: 4 rows x 8 k-units (16B each) = 128 regs
    ulonglong2 wreg[4][8];
#pragma unroll
    for (int r = 0; r < 4; r++) {
        const ulonglong2* Wg =
            (const ulonglong2*)(Whh + (size_t)(c * 8 + rg * 4 + r) * H_);
#pragma unroll
        for (int i = 0; i < 8; i++) wreg[r][i] = Wg[l + 32 * i];
    }

    // writer-lane identity: even lanes write output o=(l>>1)&15
    const bool wr  = (l & 1) == 0;
    const int  o   = (l >> 1) & 15;
    const int  ob  = bg * 4 + (o >> 2);          // batch
    const int  hrow = c * 8 + rg * 4 + (o & 3);  // global h row
    const float* WxhRow = Wxh + (size_t)hrow * V_;

    // prefetch e for t=0
    float e = 0.0f;
    if (wr) e = __ldg(WxhRow + __ldg(x_seq + ob * S_ + 0));

    const uint32_t sdst = smem_u32(hsm2);

    for (int t = 0; t < S_; t++) {
        const char* hg = (const char*)g_hbuf[t & 1];
        // stage half A: k-units [0,128) of each batch row
#pragma unroll
        for (int ii = 0; ii < 8; ii++) {
            int aidx = tid + 256 * ii;                 // 0..2047
            int b = aidx >> 7, j = aidx & 127;
            uint32_t off = (uint32_t)(b * 256 + j) * 16;
            asm volatile("cp.async.cg.shared.global [%0], [%1], 16;"
                         :: "r"(sdst + off), "l"(hg + off));
        }
        asm volatile("cp.async.commit_group;");
        // stage half B: k-units [128,256)
#pragma unroll
        for (int ii = 0; ii < 8; ii++) {
            int aidx = tid + 256 * ii;
            int b = aidx >> 7, j = 128 + (aidx & 127);
            uint32_t off = (uint32_t)(b * 256 + j) * 16;
            asm volatile("cp.async.cg.shared.global [%0], [%1], 16;"
                         :: "r"(sdst + off), "l"(hg + off));
        }
        asm volatile("cp.async.commit_group;");

        // prefetch next step's embedding (x -> Wxh chain resolves under compute)
        float e_next = 0.0f;
        if (wr && t + 1 < S_)
            e_next = __ldg(WxhRow + __ldg(x_seq + ob * S_ + (t + 1)));

        unsigned long long acc[16];
#pragma unroll
        for (int j = 0; j < 16; j++) acc[j] = 0ull;

        // ---- half A ----
        asm volatile("cp.async.wait_group 1;");
        __syncthreads();
#pragma unroll
        for (int i = 0; i < 4; i++) {
            ulonglong2 hv[4];
#pragma unroll
            for (int bi = 0; bi < 4; bi++)
                hv[bi] = hsm2[(4 * bg + bi) * 256 + l + 32 * i];
#pragma unroll
            for (int bi = 0; bi < 4; bi++)
#pragma unroll
                for (int ri = 0; ri < 4; ri++) {
                    ffma2(acc[bi * 4 + ri], hv[bi].x, wreg[ri][i].x);
                    ffma2(acc[bi * 4 + ri], hv[bi].y, wreg[ri][i].y);
                }
        }
        // ---- half B ----
        asm volatile("cp.async.wait_group 0;");
        __syncthreads();
#pragma unroll
        for (int i = 4; i < 8; i++) {
            ulonglong2 hv[4];
#pragma unroll
            for (int bi = 0; bi < 4; bi++)
                hv[bi] = hsm2[(4 * bg + bi) * 256 + l + 32 * i];
#pragma unroll
            for (int bi = 0; bi < 4; bi++)
#pragma unroll
                for (int ri = 0; ri < 4; ri++) {
                    ffma2(acc[bi * 4 + ri], hv[bi].x, wreg[ri][i].x);
                    ffma2(acc[bi * 4 + ri], hv[bi].y, wreg[ri][i].y);
                }
        }

        // merged butterfly: 16 sums over 32 lanes in 16 shfl
        float vals[16];
#pragma unroll
        for (int j = 0; j < 16; j++) vals[j] = unpack_sum(acc[j]);
#pragma unroll
        for (int off = 16; off >= 2; off >>= 1) {
            int half = off;  // live count halves in lockstep: 16,8,4,2
            bool hiSide = (l & off) != 0;
#pragma unroll
            for (int j = 0; j < 16; j++) {
                if (j < half / 1 && j < (off)) {}  // (kept simple below)
            }
            // explicit merge for this stage
#pragma unroll
            for (int j = 0; j < 8; j++) {
                if (j < (off >> 1)) {
                    float send = hiSide ? vals[j] : vals[j + (off >> 1)];
                    float recv = __shfl_xor_sync(0xffffffffu, send, off);
                    float keep = hiSide ? vals[j + (off >> 1)] : vals[j];
                    vals[j] = keep + recv;
                }
            }
        }
        vals[0] += __shfl_xor_sync(0xffffffffu, vals[0], 1);

        if (wr) {
            float hn = fw_tanh(vals[0] + e);
            g_hbuf[(t + 1) & 1][ob * H_ + hrow] = hn;
            g_Hall[((size_t)(ob * S_ + t)) * H_ + hrow] = __float2half(hn);
        }
        e = e_next;

        if (t < S_ - 1) {
            __threadfence();
            __syncthreads();
            if (tid == 0) {
                asm volatile("red.release.gpu.global.add.s32 [%0], 1;"
                             :: "l"(&g_bar[t]) : "memory");
                int v;
                do {
                    asm volatile("ld.acquire.gpu.global.s32 %0, [%1];"
                                 : "=r"(v) : "l"(&g_bar[t]) : "memory");
                } while (v < 128);
            }
            __syncthreads();
        }
    }
}

// ---------------- GEMM: logits[4096,32000] = Hall @ W16^T (fp16 in, fp32 acc) ----
// HMMA mma.sync.m16n8k16, CTA tile 128x128, BK=64, 3-stage cp.async (96KB -> 2 CTA/SM).
static constexpr int BKB    = 128;            // bytes per smem row (64 fp16)
static constexpr int ASZ    = 128 * BKB;      // 16 KB per operand tile
static constexpr int STAGE  = 2 * ASZ;        // 32 KB per stage
static constexpr int STAGES = 3;              // 96 KB dynamic smem

__global__ __launch_bounds__(256, 2) void gemm_hmma(float* __restrict__ out) {
    extern __shared__ char smc[];
    const int tid  = threadIdx.x;
    const int lane = tid & 31;
    const int warp = tid >> 5;
    const int wm   = warp >> 2;   // 0..1
    const int wn   = warp & 3;    // 0..3
    const int m0   = blockIdx.x * 128;   // m fast -> consecutive CTAs share B tile
    const int n0   = blockIdx.y * 128;
    const uint32_t sbase = smem_u32(smc);

    const char* Agb = (const char*)g_Hall + (size_t)m0 * (H_ * 2);
    const char* Bgb = (const char*)g_W16  + (size_t)n0 * (H_ * 2);

    auto issue = [&](int kb) {
        if (kb < 16) {
            uint32_t sa = sbase + (kb % STAGES) * STAGE;
            const char* Ag = Agb + kb * 128;
            const char* Bg = Bgb + kb * 128;
#pragma unroll
            for (int i = 0; i < 4; i++) {
                int chunk = tid + i * 256;
                int row = chunk >> 3, col = chunk & 7;
                uint32_t so = SW128((uint32_t)(row * BKB + col * 16));
                uint32_t d1 = sa + so;
                const char* g1 = Ag + (size_t)row * (H_ * 2) + col * 16;
                asm volatile("cp.async.cg.shared.global [%0], [%1], 16;" :: "r"(d1), "l"(g1));
                uint32_t d2 = sa + ASZ + so;
                const char* g2 = Bg + (size_t)row * (H_ * 2) + col * 16;
                asm volatile("cp.async.cg.shared.global [%0], [%1], 16;" :: "r"(d2), "l"(g2));
            }
        }
        asm volatile("cp.async.commit_group;");
    };

    issue(0); issue(1); issue(2);

    float acc[4][4][4];
#pragma unroll
    for (int mi = 0; mi < 4; mi++)
#pragma unroll
        for (int ni = 0; ni < 4; ni++)
#pragma unroll
            for (int r = 0; r < 4; r++) acc[mi][ni][r] = 0.0f;

    for (int kb = 0; kb < 16; kb++) {
        asm volatile("cp.async.wait_group 2;");
        __syncthreads();

        uint32_t sa = sbase + (kb % STAGES) * STAGE;
        uint32_t sb = sa + ASZ;

#pragma unroll
        for (int kk = 0; kk < 4; kk++) {
            uint32_t a[4][4];
#pragma unroll
            for (int mi = 0; mi < 4; mi++) {
                int row   = wm * 64 + mi * 16 + (lane & 15);
                int chunk = kk * 2 + (lane >> 4);
                uint32_t addr = sa + SW128((uint32_t)(row * BKB + chunk * 16));
                asm volatile("ldmatrix.sync.aligned.m8n8.x4.shared.b16 {%0,%1,%2,%3}, [%4];"
                             : "=r"(a[mi][0]), "=r"(a[mi][1]), "=r"(a[mi][2]), "=r"(a[mi][3])
                             : "r"(addr));
            }
            uint32_t b[4][2];
#pragma unroll
            for (int nj = 0; nj < 2; nj++) {
                int row   = wn * 32 + nj * 16 + ((lane >> 4) & 1) * 8 + (lane & 7);
                int chunk = kk * 2 + ((lane >> 3) & 1);
                uint32_t addr = sb + SW128((uint32_t)(row * BKB + chunk * 16));
                uint32_t r0, r1, r2, r3;
                asm volatile("ldmatrix.sync.aligned.m8n8.x4.shared.b16 {%0,%1,%2,%3}, [%4];"
                             : "=r"(r0), "=r"(r1), "=r"(r2), "=r"(r3) : "r"(addr));
                b[2 * nj][0] = r0; b[2 * nj][1] = r1;
                b[2 * nj + 1][0] = r2; b[2 * nj + 1][1] = r3;
            }
#pragma unroll
            for (int mi = 0; mi < 4; mi++)
#pragma unroll
                for (int ni = 0; ni < 4; ni++)
                    asm volatile(
                        "mma.sync.aligned.m16n8k16.row.col.f32.f16.f16.f32 "
                        "{%0,%1,%2,%3}, {%4,%5,%6,%7}, {%8,%9}, {%0,%1,%2,%3};"
                        : "+f"(acc[mi][ni][0]), "+f"(acc[mi][ni][1]),
                          "+f"(acc[mi][ni][2]), "+f"(acc[mi][ni][3])
                        : "r"(a[mi][0]), "r"(a[mi][1]), "r"(a[mi][2]), "r"(a[mi][3]),
                          "r"(b[ni][0]), "r"(b[ni][1]));
        }

        __syncthreads();     // everyone done reading stage kb%3 before overwrite
        issue(kb + 3);
    }

    // epilogue: direct fp32 stores
#pragma unroll
    for (int mi = 0; mi < 4; mi++) {
        int row = m0 + wm * 64 + mi * 16 + (lane >> 2);
#pragma unroll
        for (int ni = 0; ni < 4; ni++) {
            int col = n0 + wn * 32 + ni * 8 + 2 * (lane & 3);
            float* p = out + (size_t)row * V_ + col;
            *(float2*)p                    = make_float2(acc[mi][ni][0], acc[mi][ni][1]);
            *(float2*)(p + 8 * (size_t)V_) = make_float2(acc[mi][ni][2], acc[mi][ni][3]);
        }
    }
}

// ---------------- kernel: write h_final ----------------
__global__ void hfinal_kernel(float* __restrict__ out_tail) {
    int i = blockIdx.x * blockDim.x + threadIdx.x;
    if (i < B_ * H_) out_tail[i] = g_hbuf[0][i];   // t=255 wrote buffer (256)&1 = 0
}

// ---------------- launch ----------------
extern "C" void kernel_launch(void* const* d_in, const int* in_sizes, int n_in,
                              void* d_out, int out_size) {
    const int*   x_seq = (const int*)d_in[0];
    const float* Wxh   = (const float*)d_in[1];
    const float* Whh   = (const float*)d_in[2];
    const float* Why   = (const float*)d_in[3];
    float* out = (float*)d_out;

    cudaFuncSetAttribute(gemm_hmma, cudaFuncAttributeMaxDynamicSharedMemorySize,
                         STAGES * STAGE);
    cudaFuncSetAttribute(rnn_persist, cudaFuncAttributeMaxDynamicSharedMemorySize,
                         16 * H_ * (int)sizeof(float));

    cvt_why_kernel<<<512, 256>>>(Why);
    init_kernel<<<(B_ * H_ + 255) / 256, 256>>>();

    rnn_persist<<<128, 256, 16 * H_ * sizeof(float)>>>(x_seq, Wxh, Whh);

    dim3 grid((B_ * S_) / 128, V_ / 128);  // (32, 250): m fast
    gemm_hmma<<<grid, 256, STAGES * STAGE>>>(out);

    long long need = (long long)B_ * S_ * V_ + (long long)B_ * H_;
    if ((long long)out_size >= need)
        hfinal_kernel<<<(B_ * H_ + 255) / 256, 256>>>(out + (size_t)B_ * S_ * V_);
}